// round 1
// baseline (speedup 1.0000x reference)
#include <cuda_runtime.h>
#include <math_constants.h>

#define B      64
#define C      2048
#define FM     14
#define NPIX   196
#define NCHUNK 8
#define CCHUNK 256   // C / NCHUNK
#define TW     837

// scratch for per-chunk partial channel sums (no cudaMalloc allowed)
__device__ float g_partial[NCHUNK * B * NPIX];

__constant__ int d_RH[11]   = {4,3,5,6,5,7,8,6,10,7,9};
__constant__ int d_RW[11]   = {4,5,3,6,7,5,8,10,6,9,7};
__constant__ int d_WOFF[12] = {0,121,241,361,442,522,602,651,696,741,789,837};

// ---------------------------------------------------------------------------
// Kernel 1: channel-chunk reduction.  grid = (NCHUNK, B), block = 196.
// Thread t owns float4 q = t%49 (pixels 4q..4q+3), channel phase cw = t/49.
// Streaming loads (__ldcs): data is read exactly once.
// ---------------------------------------------------------------------------
__global__ void __launch_bounds__(196) appm_reduce_kernel(const float* __restrict__ x)
{
    const int chunk = blockIdx.x;
    const int b     = blockIdx.y;
    const int t     = threadIdx.x;
    const int q     = t % 49;
    const int cw    = t / 49;

    const float4* base = reinterpret_cast<const float4*>(x)
                       + ((size_t)b * C + (size_t)chunk * CCHUNK) * 49;

    float4 acc = make_float4(0.f, 0.f, 0.f, 0.f);
#pragma unroll 8
    for (int c = cw; c < CCHUNK; c += 4) {
        float4 v = __ldcs(base + (size_t)c * 49 + q);
        acc.x += v.x; acc.y += v.y; acc.z += v.z; acc.w += v.w;
    }

    __shared__ float s[NPIX];
    if (t < NPIX) s[t] = 0.f;
    __syncthreads();
    atomicAdd(&s[q * 4 + 0], acc.x);
    atomicAdd(&s[q * 4 + 1], acc.y);
    atomicAdd(&s[q * 4 + 2], acc.z);
    atomicAdd(&s[q * 4 + 3], acc.w);
    __syncthreads();
    if (t < NPIX)
        g_partial[(chunk * B + b) * NPIX + t] = s[t];
}

// ---------------------------------------------------------------------------
// Kernel 2: per-batch scores + greedy NMS.  grid = B, block = 256.
// Output layout (fp32): [B*6 indices][B*6 scores][B*837 all_scores]
// ---------------------------------------------------------------------------
__global__ void __launch_bounds__(256) appm_nms_kernel(float* __restrict__ out)
{
    const int b   = blockIdx.x;
    const int tid = threadIdx.x;

    __shared__ float  y[NPIX];
    __shared__ double SAT[FM + 1][FM + 1];
    __shared__ float  sc[TW];
    __shared__ float  cx0[TW], cy0[TW], cx1[TW], cy1[TW];
    __shared__ unsigned char valid[TW];
    __shared__ float  red_s[256];
    __shared__ int    red_i[256];
    __shared__ int    sel6[6];

    // ---- sum partials ----
    if (tid < NPIX) {
        float acc = 0.f;
#pragma unroll
        for (int ch = 0; ch < NCHUNK; ch++)
            acc += g_partial[(ch * B + b) * NPIX + tid];
        y[tid] = acc;
    }
    if (tid < FM + 1) { SAT[0][tid] = 0.0; SAT[tid][0] = 0.0; }
    __syncthreads();

    // ---- integral image (double to avoid cancellation) ----
    if (tid < FM) {
        double r = 0.0;
        for (int j = 0; j < FM; j++) {
            r += (double)y[tid * FM + j];
            SAT[tid + 1][j + 1] = r;
        }
    }
    __syncthreads();
    if (tid < FM) {
        const int j = tid;
        double r = 0.0;
        for (int i = 1; i <= FM; i++) {
            r += SAT[i][j + 1];
            SAT[i][j + 1] = r;
        }
    }
    __syncthreads();

    // ---- window scores + coords ----
    for (int w = tid; w < TW; w += 256) {
        int r = 0;
        while (w >= d_WOFF[r + 1]) r++;
        const int loc = w - d_WOFF[r];
        const int rh  = d_RH[r], rw = d_RW[r];
        const int nw  = FM - rw + 1;
        const int i   = loc / nw, j = loc % nw;
        const double s = SAT[i + rh][j + rw] - SAT[i][j + rw]
                       - SAT[i + rh][j]      + SAT[i][j];
        const float sv = (float)(s / (double)(rh * rw));
        sc[w]  = sv;
        cx0[w] = (float)(j * 32);
        cy0[w] = (float)(i * 32);
        cx1[w] = (float)((j + rw) * 32 - 1);
        cy1[w] = (float)((i + rh) * 32 - 1);
        valid[w] = 1;
        out[2 * B * 6 + (size_t)b * TW + w] = sv;   // all_scores
    }
    __syncthreads();

    // ---- greedy NMS per group ----
    const int GOFF[3] = {0, 361, 602};
    const int GW[3]   = {361, 241, 235};
    const int GN[3]   = {3, 2, 1};

    int slot = 0;
    for (int g = 0; g < 3; g++) {
        const int off = GOFF[g], W = GW[g];
        int last = 0;
        for (int step = 0; step < GN[g]; step++) {
            // parallel argmax with first-index tie-break (matches jnp.argmax)
            float bs = -CUDART_INF_F;
            int   bi = 0;
            for (int w = tid; w < W; w += 256) {
                if (valid[off + w]) {
                    const float s = sc[off + w];
                    if (s > bs) { bs = s; bi = w; }   // ascending w => first max kept
                }
            }
            red_s[tid] = bs; red_i[tid] = bi;
            __syncthreads();
            for (int o = 128; o > 0; o >>= 1) {
                if (tid < o) {
                    const float s2 = red_s[tid + o];
                    const int   i2 = red_i[tid + o];
                    if (s2 > red_s[tid] || (s2 == red_s[tid] && i2 < red_i[tid])) {
                        red_s[tid] = s2; red_i[tid] = i2;
                    }
                }
                __syncthreads();
            }
            const bool anyv = red_s[0] > -CUDART_INF_F;
            const int  idx  = anyv ? red_i[0] : last;   // torch fallback: repeat last
            if (tid == 0) sel6[slot + step] = off + idx;
            __syncthreads();

            if (anyv) {
                const float sx0 = cx0[off + idx], sy0 = cy0[off + idx];
                const float sx1 = cx1[off + idx], sy1 = cy1[off + idx];
                const float sarea = (sx1 - sx0 + 1.f) * (sy1 - sy0 + 1.f);
                for (int w = tid; w < W; w += 256) {
                    const int gw = off + w;
                    const float lx = fmaxf(cx0[gw], sx0);
                    const float ly = fmaxf(cy0[gw], sy0);
                    const float rx = fminf(cx1[gw], sx1);
                    const float ry = fminf(cy1[gw], sy1);
                    const float wx = rx - lx + 1.f;
                    const float wy = ry - ly + 1.f;
                    const float inter = (wx < 0.f || wy < 0.f) ? 0.f : wx * wy;
                    const float area  = (cx1[gw] - cx0[gw] + 1.f) * (cy1[gw] - cy0[gw] + 1.f);
                    const float iou   = inter / (area + sarea - inter);
                    if (iou > 0.25f) valid[gw] = 0;
                }
                if (tid == 0) valid[off + idx] = 0;
            }
            last = idx;
            __syncthreads();
        }
        slot += GN[g];
    }

    // ---- proposal outputs ----
    if (tid < 6) {
        const int gi = sel6[tid];
        out[(size_t)b * 6 + tid]         = (float)gi;   // proposal_indices
        out[B * 6 + (size_t)b * 6 + tid] = sc[gi];      // proposal_scores
    }
}

extern "C" void kernel_launch(void* const* d_in, const int* in_sizes, int n_in,
                              void* d_out, int out_size)
{
    const float* x = (const float*)d_in[0];
    float* out = (float*)d_out;
    appm_reduce_kernel<<<dim3(NCHUNK, B), 196>>>(x);
    appm_nms_kernel<<<B, 256>>>(out);
}

// round 2
// speedup vs baseline: 2.0987x; 2.0987x over previous
#include <cuda_runtime.h>
#include <math_constants.h>

#define B      64
#define C      2048
#define FM     14
#define NPIX   196
#define NCHUNK 16
#define CCHUNK 128   // C / NCHUNK
#define TW     837
#define MAXGW  361   // largest group window count

// scratch for per-chunk partial channel sums (no cudaMalloc allowed)
__device__ float g_partial[NCHUNK * B * NPIX];

__constant__ int d_RH[11]   = {4,3,5,6,5,7,8,6,10,7,9};
__constant__ int d_RW[11]   = {4,5,3,6,7,5,8,10,6,9,7};
__constant__ int d_WOFF[12] = {0,121,241,361,442,522,602,651,696,741,789,837};
// group meta: first ratio, window offset, window count, n_sel, slot offset
__constant__ int d_GR0[3]   = {0, 3, 6};
__constant__ int d_GOFF[3]  = {0, 361, 602};
__constant__ int d_GW[3]    = {361, 241, 235};
__constant__ int d_GN[3]    = {3, 2, 1};
__constant__ int d_GSLOT[3] = {0, 3, 5};

// ---------------------------------------------------------------------------
// Kernel 1: channel-chunk reduction.  grid = (NCHUNK, B), block = 196.
// Thread t owns float4 q = t%49 (pixels 4q..4q+3), channel phase cw = t/49.
// ---------------------------------------------------------------------------
__global__ void __launch_bounds__(196) appm_reduce_kernel(const float* __restrict__ x)
{
    const int chunk = blockIdx.x;
    const int b     = blockIdx.y;
    const int t     = threadIdx.x;
    const int q     = t % 49;
    const int cw    = t / 49;

    const float4* base = reinterpret_cast<const float4*>(x)
                       + ((size_t)b * C + (size_t)chunk * CCHUNK) * 49;

    float4 acc = make_float4(0.f, 0.f, 0.f, 0.f);
#pragma unroll 8
    for (int c = cw; c < CCHUNK; c += 4) {
        float4 v = __ldcs(base + (size_t)c * 49 + q);
        acc.x += v.x; acc.y += v.y; acc.z += v.z; acc.w += v.w;
    }

    __shared__ float s[NPIX];
    if (t < NPIX) s[t] = 0.f;
    __syncthreads();
    atomicAdd(&s[q * 4 + 0], acc.x);
    atomicAdd(&s[q * 4 + 1], acc.y);
    atomicAdd(&s[q * 4 + 2], acc.z);
    atomicAdd(&s[q * 4 + 3], acc.w);
    __syncthreads();
    if (t < NPIX)
        g_partial[(chunk * B + b) * NPIX + t] = s[t];
}

// ---------------------------------------------------------------------------
// Kernel 2: per-(batch, group) scores + greedy NMS.  grid = (B, 3), block 256.
// Output layout (fp32): [B*6 indices][B*6 scores][B*837 all_scores]
// ---------------------------------------------------------------------------
__global__ void __launch_bounds__(256) appm_nms_kernel(float* __restrict__ out)
{
    const int b   = blockIdx.x;
    const int g   = blockIdx.y;
    const int tid = threadIdx.x;
    const int lane = tid & 31;
    const int wid  = tid >> 5;

    const int goff  = d_GOFF[g];
    const int W     = d_GW[g];
    const int nsel  = d_GN[g];
    const int slot0 = d_GSLOT[g];
    const int r0    = d_GR0[g];

    __shared__ float  y[NPIX];
    __shared__ double SAT[FM + 1][FM + 1];
    __shared__ float  sc[MAXGW];
    __shared__ float  cx0[MAXGW], cy0[MAXGW], cx1[MAXGW], cy1[MAXGW];
    __shared__ unsigned char valid[MAXGW];
    __shared__ float  warp_s[8];
    __shared__ int    warp_i[8];
    __shared__ int    sel_sh;
    __shared__ int    anyv_sh;

    // ---- sum partials ----
    if (tid < NPIX) {
        float acc = 0.f;
#pragma unroll
        for (int ch = 0; ch < NCHUNK; ch++)
            acc += g_partial[(ch * B + b) * NPIX + tid];
        y[tid] = acc;
    }
    if (tid < FM + 1) { SAT[0][tid] = 0.0; SAT[tid][0] = 0.0; }
    __syncthreads();

    // ---- integral image (double; serial passes are cheap) ----
    if (tid < FM) {
        double r = 0.0;
        for (int j = 0; j < FM; j++) {
            r += (double)y[tid * FM + j];
            SAT[tid + 1][j + 1] = r;
        }
    }
    __syncthreads();
    if (tid < FM) {
        double r = 0.0;
        for (int i = 1; i <= FM; i++) {
            r += SAT[i][tid + 1];
            SAT[i][tid + 1] = r;
        }
    }
    __syncthreads();

    // ---- window scores + coords for THIS group (float divide, no FP64 div) ----
    for (int w = tid; w < W; w += 256) {
        const int gw = goff + w;
        int r = r0;
        while (gw >= d_WOFF[r + 1]) r++;
        const int loc = gw - d_WOFF[r];
        const int rh  = d_RH[r], rw = d_RW[r];
        const int nw  = FM - rw + 1;
        const int i   = loc / nw, j = loc % nw;
        const float s = (float)(SAT[i + rh][j + rw] - SAT[i][j + rw]
                              - SAT[i + rh][j]      + SAT[i][j]);
        const float sv = s / (float)(rh * rw);
        sc[w]  = sv;
        cx0[w] = (float)(j * 32);
        cy0[w] = (float)(i * 32);
        cx1[w] = (float)((j + rw) * 32 - 1);
        cy1[w] = (float)((i + rh) * 32 - 1);
        valid[w] = 1;
        out[2 * B * 6 + (size_t)b * TW + gw] = sv;   // all_scores
    }
    __syncthreads();

    // ---- greedy NMS for this group ----
    int last = 0;
    for (int step = 0; step < nsel; step++) {
        // per-thread scan
        float bs = -CUDART_INF_F;
        int   bi = MAXGW;
        for (int w = tid; w < W; w += 256) {
            if (valid[w]) {
                const float s = sc[w];
                if (s > bs) { bs = s; bi = w; }   // ascending w => first max kept
            }
        }
        // warp reduce (keep lowest index on ties)
#pragma unroll
        for (int o = 16; o > 0; o >>= 1) {
            const float s2 = __shfl_down_sync(0xffffffffu, bs, o);
            const int   i2 = __shfl_down_sync(0xffffffffu, bi, o);
            if (s2 > bs || (s2 == bs && i2 < bi)) { bs = s2; bi = i2; }
        }
        if (lane == 0) { warp_s[wid] = bs; warp_i[wid] = bi; }
        __syncthreads();
        if (tid == 0) {
            float fs = warp_s[0]; int fi = warp_i[0];
#pragma unroll
            for (int k = 1; k < 8; k++) {
                const float s2 = warp_s[k]; const int i2 = warp_i[k];
                if (s2 > fs || (s2 == fs && i2 < fi)) { fs = s2; fi = i2; }
            }
            const bool anyv = fs > -CUDART_INF_F;
            anyv_sh = anyv ? 1 : 0;
            sel_sh  = anyv ? fi : last;          // torch fallback: repeat last
        }
        __syncthreads();
        const int idx = sel_sh;
        if (tid == 0)
            out[(size_t)b * 6 + slot0 + step] = (float)(goff + idx);
        if (tid == 1)
            out[B * 6 + (size_t)b * 6 + slot0 + step] = sc[idx];

        if (anyv_sh) {
            const float sx0 = cx0[idx], sy0 = cy0[idx];
            const float sx1 = cx1[idx], sy1 = cy1[idx];
            const float sarea = (sx1 - sx0 + 1.f) * (sy1 - sy0 + 1.f);
            for (int w = tid; w < W; w += 256) {
                const float lx = fmaxf(cx0[w], sx0);
                const float ly = fmaxf(cy0[w], sy0);
                const float rx = fminf(cx1[w], sx1);
                const float ry = fminf(cy1[w], sy1);
                const float wx = rx - lx + 1.f;
                const float wy = ry - ly + 1.f;
                const float inter = (wx < 0.f || wy < 0.f) ? 0.f : wx * wy;
                const float area  = (cx1[w] - cx0[w] + 1.f) * (cy1[w] - cy0[w] + 1.f);
                const float iou   = inter / (area + sarea - inter);
                if (iou > 0.25f) valid[w] = 0;
            }
            if (tid == 0) valid[idx] = 0;
        }
        last = idx;
        __syncthreads();
    }
}

extern "C" void kernel_launch(void* const* d_in, const int* in_sizes, int n_in,
                              void* d_out, int out_size)
{
    const float* x = (const float*)d_in[0];
    float* out = (float*)d_out;
    appm_reduce_kernel<<<dim3(NCHUNK, B), 196>>>(x);
    appm_nms_kernel<<<dim3(B, 3), 256>>>(out);
}